// round 9
// baseline (speedup 1.0000x reference)
#include <cuda_runtime.h>
#include <cstdint>
#include <math.h>

#define HEADS 8
#define HD    64
#define BB    2
#define LL    2048
#define DD    512
#define OC    1536   // 3*HEADS*HD

// Scratch (device globals — no allocations allowed)
__device__ float g_qkv [BB * OC * LL];   // conv+swish output, [b, c, l]
__device__ float g_newv[BB * LL * DD];   // attention output, [b, l, h*HD+d]
__device__ float g_fc  [BB * LL * DD];   // fc+swish output,  [b, l, d]
__device__ float g_wt  [3 * OC * DD];    // transposed conv weights [t][o][i]

__device__ __forceinline__ float swishf(float v) {
    return v / (1.f + __expf(-v));
}
__device__ __forceinline__ uint32_t smem_u32(const void* p) {
    return (uint32_t)__cvta_generic_to_shared(p);
}
__device__ __forceinline__ void cpa16(uint32_t dst, const void* src) {
    asm volatile("cp.async.cg.shared.global [%0], [%1], 16;" :: "r"(dst), "l"(src));
}
__device__ __forceinline__ void cpa16p(uint32_t dst, const void* src, bool pred) {
    int sz = pred ? 16 : 0;
    asm volatile("cp.async.cg.shared.global [%0], [%1], 16, %2;" :: "r"(dst), "l"(src), "r"(sz));
}
#define CPC()      asm volatile("cp.async.commit_group;" ::: "memory")
#define CP_WAIT0() asm volatile("cp.async.wait_group 0;" ::: "memory")
#define CP_WAIT1() asm volatile("cp.async.wait_group 1;" ::: "memory")

// m16n8k8 tf32 mma
__device__ __forceinline__ void mma_tf32(float c[4], const uint32_t a[4], const uint32_t b[2]) {
    asm volatile(
        "mma.sync.aligned.m16n8k8.row.col.f32.tf32.tf32.f32 "
        "{%0,%1,%2,%3}, {%4,%5,%6,%7}, {%8,%9}, {%0,%1,%2,%3};"
        : "+f"(c[0]), "+f"(c[1]), "+f"(c[2]), "+f"(c[3])
        : "r"(a[0]), "r"(a[1]), "r"(a[2]), "r"(a[3]), "r"(b[0]), "r"(b[1]));
}
__device__ __forceinline__ void ldsm4(uint32_t r[4], uint32_t addr) {
    asm volatile("ldmatrix.sync.aligned.m8n8.x4.shared.b16 {%0,%1,%2,%3}, [%4];"
        : "=r"(r[0]), "=r"(r[1]), "=r"(r[2]), "=r"(r[3]) : "r"(addr));
}
__device__ __forceinline__ void ldsm2(uint32_t r[2], uint32_t addr) {
    asm volatile("ldmatrix.sync.aligned.m8n8.x2.shared.b16 {%0,%1}, [%2];"
        : "=r"(r[0]), "=r"(r[1]) : "r"(addr));
}

// ---------------------------------------------------------------------------
// Kernel 0: transpose conv weights to [t][o][i]. Contiguous 12B reads.
// ---------------------------------------------------------------------------
__global__ void wprep_kernel(const float* __restrict__ w)
{
    int idx = blockIdx.x * 256 + threadIdx.x;     // over OC*DD
    if (idx < OC * DD) {
        int i = idx & 511;
        int o = idx >> 9;
        const float* src = w + (size_t)o * 1536 + i * 3;
        g_wt[idx]                   = src[0];
        g_wt[OC * DD + idx]         = src[1];
        g_wt[2 * OC * DD + idx]     = src[2];
    }
}

// ---------------------------------------------------------------------------
// Kernel 1 (mma.sync tf32 + cp.async + ldmatrix):
// Conv1d(D->OC,k=3,pad=1)+bias+swish -> g_qkv[b][o][l]
// Tile 128(o) x 256(l), 512 threads (16 warps: wm 0..1 x wn 0..7, warp 64x32).
// smem: A[2][128][36] + B[2][256][36] = 108 KB.
// ---------------------------------------------------------------------------
#define CONV_SMEM ((2 * 128 * 36 + 2 * 256 * 36) * 4)

__device__ __forceinline__ void conv_issue(float* dsm, int buf, int c, int b,
                                           int o0, int l0,
                                           const float* __restrict__ x, int tid)
{
    const int t  = c >> 4;
    const int i0 = (c & 15) * 32;
    const float* wt = g_wt + ((size_t)t * OC + o0) * DD + i0;
    float* sA = dsm + buf * 4608;
    float* sB = dsm + 9216 + buf * 9216;
    #pragma unroll
    for (int r = 0; r < 2; r++) {
        int idx = tid + r * 512;        // 0..1023
        int m = idx >> 3, kq = (idx & 7) * 4;
        cpa16(smem_u32(&sA[m * 36 + kq]), wt + (size_t)m * DD + kq);
    }
    #pragma unroll
    for (int r = 0; r < 4; r++) {
        int idx = tid + r * 512;        // 0..2047
        int n = idx >> 3, kq = (idx & 7) * 4;
        int l = l0 + n + t - 1;
        bool ok = (l >= 0) && (l < LL);
        const float* src = ok ? (x + ((size_t)(b * LL + l)) * DD + i0 + kq) : x;
        cpa16p(smem_u32(&sB[n * 36 + kq]), src, ok);
    }
}

__global__ void __launch_bounds__(512, 1) conv_mma_kernel(const float* __restrict__ x,
                                                          const float* __restrict__ bias)
{
    extern __shared__ float dsm[];

    const int b   = blockIdx.z;
    const int l0  = blockIdx.x * 256;
    const int o0  = blockIdx.y * 128;
    const int tid = threadIdx.x;
    const int wid = tid >> 5;
    const int lane = tid & 31;
    const int g   = lane >> 2;
    const int tg  = lane & 3;
    const int wm  = wid & 1;          // 0..1 -> 64 o-rows
    const int wn  = wid >> 1;         // 0..7 -> 32 l-cols
    const int lr  = lane & 7;
    const int ls1 = (lane >> 3) & 1;
    const int ls2 = lane >> 4;

    float acc[4][4][4];
    #pragma unroll
    for (int mi = 0; mi < 4; mi++)
        #pragma unroll
        for (int ni = 0; ni < 4; ni++)
            #pragma unroll
            for (int q = 0; q < 4; q++) acc[mi][ni][q] = 0.f;

    conv_issue(dsm, 0, 0, b, o0, l0, x, tid);
    CPC();

    for (int c = 0; c < 48; c++) {
        const int cur = c & 1;
        if (c < 47) {
            conv_issue(dsm, cur ^ 1, c + 1, b, o0, l0, x, tid);
            CPC();
            CP_WAIT1();
        } else {
            CP_WAIT0();
        }
        __syncthreads();

        const float* A  = dsm + cur * 4608;
        const float* Bm = dsm + 9216 + cur * 9216;

        #pragma unroll
        for (int ks = 0; ks < 4; ks++) {
            const int k0 = ks * 8;
            uint32_t af[4][4], bf[4][2];
            #pragma unroll
            for (int mi = 0; mi < 4; mi++) {
                int row = wm * 64 + mi * 16 + ls1 * 8 + lr;
                ldsm4(af[mi], smem_u32(&A[row * 36 + k0 + ls2 * 4]));
            }
            #pragma unroll
            for (int ni = 0; ni < 4; ni++) {
                int row = wn * 32 + ni * 8 + lr;
                ldsm2(bf[ni], smem_u32(&Bm[row * 36 + k0 + ls1 * 4]));
            }
            #pragma unroll
            for (int mi = 0; mi < 4; mi++)
                #pragma unroll
                for (int ni = 0; ni < 4; ni++)
                    mma_tf32(acc[mi][ni], af[mi], bf[ni]);
        }
        __syncthreads();
    }

    #pragma unroll
    for (int mi = 0; mi < 4; mi++) {
        int o_lo = o0 + wm * 64 + mi * 16 + g;
        int o_hi = o_lo + 8;
        float b_lo = bias[o_lo], b_hi = bias[o_hi];
        float* row_lo = g_qkv + ((size_t)b * OC + o_lo) * LL;
        float* row_hi = g_qkv + ((size_t)b * OC + o_hi) * LL;
        #pragma unroll
        for (int ni = 0; ni < 4; ni++) {
            int l = l0 + wn * 32 + ni * 8 + 2 * tg;
            float2 v0, v1;
            v0.x = swishf(acc[mi][ni][0] + b_lo);
            v0.y = swishf(acc[mi][ni][1] + b_lo);
            v1.x = swishf(acc[mi][ni][2] + b_hi);
            v1.y = swishf(acc[mi][ni][3] + b_hi);
            *reinterpret_cast<float2*>(&row_lo[l]) = v0;
            *reinterpret_cast<float2*>(&row_hi[l]) = v1;
        }
    }
}

// ---------------------------------------------------------------------------
// Kernel 2: flash attention, register-resident softmax.
// CTA = (b, h, 256-row w tile), 512 threads (wm 0..7 x wn 0..1).
// Q [w][d] pre-scaled; K [d][m]; V [dd][m]; P stored once (exp'd) for ldsm.
// Running max/denom kept in REGISTERS (all owner threads compute identically);
// cross-warp (wn pair) exchange via 2KB smem arrays.
// ---------------------------------------------------------------------------
#define QST 68
#define KST 72
#define VST 68
#define PST 68
#define ATTN_SMEM ((256*QST + 2*64*KST + 2*64*VST + 256*PST + 4*256) * 4)

__device__ __forceinline__ void attn_issue_kv(float* sK, float* sV, int buf,
                                              const float* __restrict__ kbase,
                                              const float* __restrict__ vbase,
                                              int m0, int tid)
{
    float* k = sK + buf * 64 * KST;
    float* v = sV + buf * 64 * VST;
    #pragma unroll
    for (int r = 0; r < 2; r++) {
        int idx = tid + r * 512;
        int dd = idx >> 4;
        int ms = (idx & 15) * 4;
        cpa16(smem_u32(&k[dd * KST + ms]), kbase + (size_t)dd * LL + m0 + ms);
    }
    #pragma unroll
    for (int r = 0; r < 2; r++) {
        int idx = tid + r * 512;
        int dd = idx >> 4;
        int ms = (idx & 15) * 4;
        cpa16(smem_u32(&v[dd * VST + ms]), vbase + (size_t)dd * LL + m0 + ms);
    }
}

__global__ void __launch_bounds__(512, 1) attn_mma_kernel()
{
    extern __shared__ float dsm[];
    float* sQ  = dsm;                      // [256][QST]  (w, d) pre-scaled
    float* sK  = sQ + 256 * QST;           // [2][64][KST] (d, m)
    float* sV  = sK + 2 * 64 * KST;        // [2][64][VST] (dd, m)
    float* sP  = sV + 2 * 64 * VST;        // [256][PST]  (w, m) exp'd probs
    float* sExM = sP + 256 * PST;          // [256][2] partial max (row, wn)
    float* sExS = sExM + 512;              // [256][2] partial sum

    const int b   = blockIdx.z;
    const int h   = blockIdx.y;
    const int w0  = blockIdx.x * 256;
    const int tid = threadIdx.x;
    const int wid = tid >> 5;
    const int lane = tid & 31;
    const int g   = lane >> 2;
    const int tg  = lane & 3;
    const int wm  = wid & 7;        // 0..7 -> 32 w-rows each
    const int wn  = wid >> 3;       // 0..1 -> 32 cols each
    const int lr  = lane & 7;
    const int ls1 = (lane >> 3) & 1;
    const int ls2 = lane >> 4;

    const float scale = rsqrtf((float)LL);
    const float* qbase = g_qkv + ((size_t)b * OC + h * 192) * LL;
    const float* kbase = qbase + (size_t)64 * LL;
    const float* vbase = qbase + (size_t)128 * LL;

    attn_issue_kv(sK, sV, 0, kbase, vbase, 0, tid);
    CPC();

    // Q tile: [256 w][64 d], transposed scalar fill, pre-scaled
    #pragma unroll
    for (int r = 0; r < 32; r++) {
        int idx = tid + r * 512;
        int ww = idx & 255;
        int dd = idx >> 8;
        sQ[ww * QST + dd] = qbase[(size_t)dd * LL + w0 + ww] * scale;
    }

    // Per-thread running softmax state for its 4 rows (mi x lo/hi)
    float m_run[4], l_run[4];
    #pragma unroll
    for (int rr = 0; rr < 4; rr++) { m_run[rr] = -1e30f; l_run[rr] = 0.f; }

    float acc_o[2][4][4];
    #pragma unroll
    for (int mi = 0; mi < 2; mi++)
        #pragma unroll
        for (int ni = 0; ni < 4; ni++)
            #pragma unroll
            for (int q = 0; q < 4; q++) acc_o[mi][ni][q] = 0.f;

    CP_WAIT0();
    __syncthreads();

    for (int c = 0; c < 32; c++) {
        const int cur = c & 1;
        if (c < 31) {
            attn_issue_kv(sK, sV, cur ^ 1, kbase, vbase, (c + 1) * 64, tid);
            CPC();
        }
        const float* K = sK + cur * 64 * KST;
        const float* V = sV + cur * 64 * VST;

        // GEMM1: S[256 w][64 m] = Q K^T (k = d = 64); Q pre-scaled.
        float acc_s[2][4][4];
        #pragma unroll
        for (int mi = 0; mi < 2; mi++)
            #pragma unroll
            for (int ni = 0; ni < 4; ni++)
                #pragma unroll
                for (int q = 0; q < 4; q++) acc_s[mi][ni][q] = 0.f;

        #pragma unroll
        for (int ks = 0; ks < 8; ks++) {
            const int k0 = ks * 8;
            uint32_t af[2][4], bf[4][2];
            #pragma unroll
            for (int mi = 0; mi < 2; mi++) {
                int row = wm * 32 + mi * 16 + ls1 * 8 + lr;
                ldsm4(af[mi], smem_u32(&sQ[row * QST + k0 + ls2 * 4]));
            }
            #pragma unroll
            for (int ni = 0; ni < 4; ni++) {
                int n = wn * 32 + ni * 8 + g;
                bf[ni][0] = __float_as_uint(K[(k0 + tg    ) * KST + n]);
                bf[ni][1] = __float_as_uint(K[(k0 + tg + 4) * KST + n]);
            }
            #pragma unroll
            for (int mi = 0; mi < 2; mi++)
                #pragma unroll
                for (int ni = 0; ni < 4; ni++)
                    mma_tf32(acc_s[mi][ni], af[mi], bf[ni]);
        }

        // Register softmax, stage 1: per-warp partial row max (32 cols)
        float pmax[4];
        #pragma unroll
        for (int mi = 0; mi < 2; mi++) {
            float mlo = acc_s[mi][0][0], mhi = acc_s[mi][0][2];
            mlo = fmaxf(mlo, acc_s[mi][0][1]);
            mhi = fmaxf(mhi, acc_s[mi][0][3]);
            #pragma unroll
            for (int ni = 1; ni < 4; ni++) {
                mlo = fmaxf(mlo, fmaxf(acc_s[mi][ni][0], acc_s[mi][ni][1]));
                mhi = fmaxf(mhi, fmaxf(acc_s[mi][ni][2], acc_s[mi][ni][3]));
            }
            pmax[mi * 2]     = mlo;
            pmax[mi * 2 + 1] = mhi;
        }
        #pragma unroll
        for (int rr = 0; rr < 4; rr++) {
            pmax[rr] = fmaxf(pmax[rr], __shfl_xor_sync(0xffffffff, pmax[rr], 1));
            pmax[rr] = fmaxf(pmax[rr], __shfl_xor_sync(0xffffffff, pmax[rr], 2));
        }
        if (tg == 0) {
            #pragma unroll
            for (int rr = 0; rr < 4; rr++) {
                int row = wm * 32 + (rr >> 1) * 16 + (rr & 1) * 8 + g;
                sExM[row * 2 + wn] = pmax[rr];
            }
        }
        __syncthreads();

        // Stage 2: combine max, exp in regs, store P, partial sums
        float mx[4], sc[4], psum[4];
        #pragma unroll
        for (int rr = 0; rr < 4; rr++) {
            int row = wm * 32 + (rr >> 1) * 16 + (rr & 1) * 8 + g;
            float m2 = fmaxf(sExM[row * 2], sExM[row * 2 + 1]);
            float mxv = fmaxf(m2, m_run[rr]);
            sc[rr] = __expf(m_run[rr] - mxv);
            m_run[rr] = mxv;
            mx[rr] = mxv;
            psum[rr] = 0.f;
        }
        #pragma unroll
        for (int mi = 0; mi < 2; mi++) {
            int r_lo = wm * 32 + mi * 16 + g;
            int r_hi = r_lo + 8;
            #pragma unroll
            for (int ni = 0; ni < 4; ni++) {
                float e0 = __expf(acc_s[mi][ni][0] - mx[mi * 2]);
                float e1 = __expf(acc_s[mi][ni][1] - mx[mi * 2]);
                float e2 = __expf(acc_s[mi][ni][2] - mx[mi * 2 + 1]);
                float e3 = __expf(acc_s[mi][ni][3] - mx[mi * 2 + 1]);
                psum[mi * 2]     += e0 + e1;
                psum[mi * 2 + 1] += e2 + e3;
                int cc = wn * 32 + ni * 8 + 2 * tg;
                *reinterpret_cast<float2*>(&sP[r_lo * PST + cc]) = make_float2(e0, e1);
                *reinterpret_cast<float2*>(&sP[r_hi * PST + cc]) = make_float2(e2, e3);
            }
        }
        #pragma unroll
        for (int rr = 0; rr < 4; rr++) {
            psum[rr] += __shfl_xor_sync(0xffffffff, psum[rr], 1);
            psum[rr] += __shfl_xor_sync(0xffffffff, psum[rr], 2);
        }
        if (tg == 0) {
            #pragma unroll
            for (int rr = 0; rr < 4; rr++) {
                int row = wm * 32 + (rr >> 1) * 16 + (rr & 1) * 8 + g;
                sExS[row * 2 + wn] = psum[rr];
            }
        }
        __syncthreads();

        // Stage 3: finalize denom, rescale O accumulators
        #pragma unroll
        for (int rr = 0; rr < 4; rr++) {
            int row = wm * 32 + (rr >> 1) * 16 + (rr & 1) * 8 + g;
            float tot = sExS[row * 2] + sExS[row * 2 + 1];
            l_run[rr] = l_run[rr] * sc[rr] + tot;
        }
        #pragma unroll
        for (int mi = 0; mi < 2; mi++) {
            float s0 = sc[mi * 2], s1 = sc[mi * 2 + 1];
            #pragma unroll
            for (int ni = 0; ni < 4; ni++) {
                acc_o[mi][ni][0] *= s0; acc_o[mi][ni][1] *= s0;
                acc_o[mi][ni][2] *= s1; acc_o[mi][ni][3] *= s1;
            }
        }

        // GEMM2: O[256 w][64 dd] += P V^T (k = m = 64)
        #pragma unroll
        for (int ks = 0; ks < 8; ks++) {
            const int k0 = ks * 8;
            uint32_t af[2][4], bf[4][2];
            #pragma unroll
            for (int mi = 0; mi < 2; mi++) {
                int row = wm * 32 + mi * 16 + ls1 * 8 + lr;
                ldsm4(af[mi], smem_u32(&sP[row * PST + k0 + ls2 * 4]));
            }
            #pragma unroll
            for (int ni = 0; ni < 4; ni++) {
                int row = wn * 32 + ni * 8 + lr;
                ldsm2(bf[ni], smem_u32(&V[row * VST + k0 + ls1 * 4]));
            }
            #pragma unroll
            for (int mi = 0; mi < 2; mi++)
                #pragma unroll
                for (int ni = 0; ni < 4; ni++)
                    mma_tf32(acc_o[mi][ni], af[mi], bf[ni]);
        }
        CP_WAIT0();
        __syncthreads();
    }

    // Final: O /= L (register denom), write g_newv
    #pragma unroll
    for (int mi = 0; mi < 2; mi++) {
        int r_lo = wm * 32 + mi * 16 + g;
        int r_hi = r_lo + 8;
        float inv0 = 1.f / l_run[mi * 2];
        float inv1 = 1.f / l_run[mi * 2 + 1];
        float* out_lo = g_newv + ((size_t)(b * LL) + w0 + r_lo) * DD + h * HD;
        float* out_hi = g_newv + ((size_t)(b * LL) + w0 + r_hi) * DD + h * HD;
        #pragma unroll
        for (int ni = 0; ni < 4; ni++) {
            int cc = wn * 32 + ni * 8 + 2 * tg;
            *reinterpret_cast<float2*>(&out_lo[cc]) =
                make_float2(acc_o[mi][ni][0] * inv0, acc_o[mi][ni][1] * inv0);
            *reinterpret_cast<float2*>(&out_hi[cc]) =
                make_float2(acc_o[mi][ni][2] * inv1, acc_o[mi][ni][3] * inv1);
        }
    }
}

// ---------------------------------------------------------------------------
// Kernel 3 (mma.sync tf32 + cp.async + ldmatrix): m = swish(new_v@fc_w^T+fc_b)
// ---------------------------------------------------------------------------
#define FC_SMEM (4 * 128 * 36 * 4)

__device__ __forceinline__ void fc_issue(float* dsm, int buf, int c, int m0, int n0,
                                         const float* __restrict__ fw, int tid)
{
    const int k0g = c * 32;
    float* sA = dsm + buf * 4608;
    float* sB = dsm + 9216 + buf * 4608;
    #pragma unroll
    for (int r = 0; r < 4; r++) {
        int idx = tid + r * 256;
        int m = idx >> 3, kq = (idx & 7) * 4;
        cpa16(smem_u32(&sA[m * 36 + kq]), g_newv + (size_t)(m0 + m) * DD + k0g + kq);
    }
    #pragma unroll
    for (int r = 0; r < 4; r++) {
        int idx = tid + r * 256;
        int n = idx >> 3, kq = (idx & 7) * 4;
        cpa16(smem_u32(&sB[n * 36 + kq]), fw + (size_t)(n0 + n) * DD + k0g + kq);
    }
}

__global__ void __launch_bounds__(256, 2) fc_mma_kernel(const float* __restrict__ fw,
                                                        const float* __restrict__ fb)
{
    extern __shared__ float dsm[];

    const int m0  = blockIdx.x * 128;
    const int n0  = blockIdx.y * 128;
    const int tid = threadIdx.x;
    const int wid = tid >> 5;
    const int lane = tid & 31;
    const int g   = lane >> 2;
    const int tg  = lane & 3;
    const int wm  = wid & 1;
    const int wn  = wid >> 1;
    const int lr  = lane & 7;
    const int ls1 = (lane >> 3) & 1;
    const int ls2 = lane >> 4;

    float acc[4][4][4];
    #pragma unroll
    for (int mi = 0; mi < 4; mi++)
        #pragma unroll
        for (int ni = 0; ni < 4; ni++)
            #pragma unroll
            for (int q = 0; q < 4; q++) acc[mi][ni][q] = 0.f;

    fc_issue(dsm, 0, 0, m0, n0, fw, tid);
    CPC();

    for (int c = 0; c < 16; c++) {
        const int cur = c & 1;
        if (c < 15) {
            fc_issue(dsm, cur ^ 1, c + 1, m0, n0, fw, tid);
            CPC();
            CP_WAIT1();
        } else {
            CP_WAIT0();
        }
        __syncthreads();

        const float* A  = dsm + cur * 4608;
        const float* Bm = dsm + 9216 + cur * 4608;

        #pragma unroll
        for (int ks = 0; ks < 4; ks++) {
            const int k0 = ks * 8;
            uint32_t af[4][4], bf[4][2];
            #pragma unroll
            for (int mi = 0; mi < 4; mi++) {
                int row = wm * 64 + mi * 16 + ls1 * 8 + lr;
                ldsm4(af[mi], smem_u32(&A[row * 36 + k0 + ls2 * 4]));
            }
            #pragma unroll
            for (int ni = 0; ni < 4; ni++) {
                int row = wn * 32 + ni * 8 + lr;
                ldsm2(bf[ni], smem_u32(&Bm[row * 36 + k0 + ls1 * 4]));
            }
            #pragma unroll
            for (int mi = 0; mi < 4; mi++)
                #pragma unroll
                for (int ni = 0; ni < 4; ni++)
                    mma_tf32(acc[mi][ni], af[mi], bf[ni]);
        }
        __syncthreads();
    }

    #pragma unroll
    for (int mi = 0; mi < 4; mi++) {
        int m_lo = m0 + wm * 64 + mi * 16 + g;
        int m_hi = m_lo + 8;
        #pragma unroll
        for (int ni = 0; ni < 4; ni++) {
            int n = n0 + wn * 32 + ni * 8 + 2 * tg;
            float b0 = fb[n], b1 = fb[n + 1];
            float2 v0, v1;
            v0.x = swishf(acc[mi][ni][0] + b0);
            v0.y = swishf(acc[mi][ni][1] + b1);
            v1.x = swishf(acc[mi][ni][2] + b0);
            v1.y = swishf(acc[mi][ni][3] + b1);
            *reinterpret_cast<float2*>(&g_fc[(size_t)m_lo * DD + n]) = v0;
            *reinterpret_cast<float2*>(&g_fc[(size_t)m_hi * DD + n]) = v1;
        }
    }
}

// ---------------------------------------------------------------------------
// Kernel 4: out = layer_norm(2*x + g_fc). One warp per row, float4.
// ---------------------------------------------------------------------------
__global__ void ln_kernel(const float* __restrict__ x,
                          float* __restrict__ out)
{
    const int row  = blockIdx.x * 8 + (threadIdx.x >> 5);
    const int lane = threadIdx.x & 31;
    const float4* mrow = reinterpret_cast<const float4*>(g_fc + (size_t)row * DD);
    const float4* xrow = reinterpret_cast<const float4*>(x    + (size_t)row * DD);

    float4 tv[4];
    float sum = 0.f, sq = 0.f;
    #pragma unroll
    for (int t = 0; t < 4; t++) {
        int d = lane + 32 * t;
        float4 xv = xrow[d];
        float4 mv = mrow[d];
        float4 v;
        v.x = 2.f * xv.x + mv.x;
        v.y = 2.f * xv.y + mv.y;
        v.z = 2.f * xv.z + mv.z;
        v.w = 2.f * xv.w + mv.w;
        tv[t] = v;
        sum += v.x + v.y + v.z + v.w;
        sq  += v.x * v.x + v.y * v.y + v.z * v.z + v.w * v.w;
    }
    #pragma unroll
    for (int off = 16; off >= 1; off >>= 1) {
        sum += __shfl_xor_sync(0xffffffff, sum, off);
        sq  += __shfl_xor_sync(0xffffffff, sq,  off);
    }
    float mu  = sum * (1.f / 512.f);
    float var = sq * (1.f / 512.f) - mu * mu;
    float inv = rsqrtf(var + 1e-5f);

    float4* orow = reinterpret_cast<float4*>(out + (size_t)row * DD);
    #pragma unroll
    for (int t = 0; t < 4; t++) {
        float4 v = tv[t];
        float4 o;
        o.x = (v.x - mu) * inv;
        o.y = (v.y - mu) * inv;
        o.z = (v.z - mu) * inv;
        o.w = (v.w - mu) * inv;
        orow[lane + 32 * t] = o;
    }
}

// ---------------------------------------------------------------------------
extern "C" void kernel_launch(void* const* d_in, const int* in_sizes, int n_in,
                              void* d_out, int out_size)
{
    const float* x  = (const float*)d_in[0];
    const float* cw = (const float*)d_in[1];
    const float* cb = (const float*)d_in[2];
    const float* fw = (const float*)d_in[3];
    const float* fb = (const float*)d_in[4];
    float* out = (float*)d_out;

    cudaFuncSetAttribute(conv_mma_kernel,
                         cudaFuncAttributeMaxDynamicSharedMemorySize, CONV_SMEM);
    cudaFuncSetAttribute(attn_mma_kernel,
                         cudaFuncAttributeMaxDynamicSharedMemorySize, ATTN_SMEM);
    cudaFuncSetAttribute(fc_mma_kernel,
                         cudaFuncAttributeMaxDynamicSharedMemorySize, FC_SMEM);

    // 0) transpose weights (contiguous tap reads)
    wprep_kernel<<<(OC * DD + 255) / 256, 256>>>(cw);

    // 1) conv+swish, tile 128x256, 512 threads
    dim3 cgrid(LL / 256, OC / 128, BB);
    conv_mma_kernel<<<cgrid, 512, CONV_SMEM>>>(x, cb);

    // 2) attention, register softmax
    dim3 agrid(LL / 256, HEADS, BB);
    attn_mma_kernel<<<agrid, 512, ATTN_SMEM>>>();

    // 3) fc + swish
    dim3 fgrid((BB * LL) / 128, DD / 128);
    fc_mma_kernel<<<fgrid, 256, FC_SMEM>>>(fw, fb);

    // 4) residual + layernorm
    ln_kernel<<<(BB * LL) / 8, 256>>>(x, out);
}